// round 1
// baseline (speedup 1.0000x reference)
#include <cuda_runtime.h>
#include <math.h>

#define BB 32
#define HH 128
#define WW 128
#define CC 64
#define MX 16
#define MY 16
#define NK 17   // H-axis partial DFT rows k = 0..16 (negatives via conjugate symmetry)

// ---------------- scratch (device globals; no allocation allowed) ----------------
__device__ __align__(16) float g_X1re[BB*NK*WW*CC];
__device__ __align__(16) float g_X1im[BB*NK*WW*CC];
__device__ __align__(16) float g_Yre[BB*32*MY*CC];
__device__ __align__(16) float g_Yim[BB*32*MY*CC];
__device__ __align__(16) float g_Gre[BB*MY*32*CC];   // [b][ky][r][c]
__device__ __align__(16) float g_Gim[BB*MY*32*CC];
__device__ __align__(16) float g_Mre[BB*MY*HH*CC];   // [b][ky][h][c]
__device__ __align__(16) float g_Mim[BB*MY*HH*CC];

__device__ __align__(16) float g_TA[HH*36];          // [h][k0..17 pairs (cos,sin)], k=17 zero pad
__device__ __align__(16) float g_TB[WW*32];          // [w][ky0..15 pairs (cos,sin)]
__device__ __align__(16) float g_TD1[32*HH*2];       // [r][h] pairs e^{+2pi i kx(r) h/128}
__device__ __align__(16) float g_TC[WW*16];          // [w][ky] c_ky*cos/16384
__device__ __align__(16) float g_TS[WW*16];          // [w][ky] c_ky*sin/16384

// ---------------- twiddle init ----------------
__global__ void k_init() {
    int t = blockIdx.x * blockDim.x + threadIdx.x;
    int stride = gridDim.x * blockDim.x;
    const float STEP = 6.28318530717958647692f / 128.0f;

    for (int i = t; i < HH*18; i += stride) {
        int h = i / 18, k = i % 18;
        float c = 0.f, s = 0.f;
        if (k < 17) { int m = (k * h) & 127; sincosf(STEP * (float)m, &s, &c); }
        g_TA[h*36 + 2*k]     = c;
        g_TA[h*36 + 2*k + 1] = s;
    }
    for (int i = t; i < WW*16; i += stride) {
        int w = i / 16, ky = i % 16;
        int m = (ky * w) & 127;
        float s, c; sincosf(STEP * (float)m, &s, &c);
        g_TB[(w*16 + ky)*2]     = c;
        g_TB[(w*16 + ky)*2 + 1] = s;
    }
    for (int i = t; i < 32*HH; i += stride) {
        int r = i / HH, h = i % HH;
        int kx = (r < 16) ? r : (r - 32);
        int m = (((kx * h) % 128) + 128) & 127;
        float s, c; sincosf(STEP * (float)m, &s, &c);
        g_TD1[i*2]     = c;
        g_TD1[i*2 + 1] = s;
    }
    for (int i = t; i < WW*16; i += stride) {
        int w = i / 16, ky = i % 16;
        int m = (ky * w) & 127;
        float s, c; sincosf(STEP * (float)m, &s, &c);
        float coef = ((ky == 0) ? 1.f : 2.f) / 16384.f;
        g_TC[w*16 + ky] = coef * c;
        g_TS[w*16 + ky] = coef * s;
    }
}

// ---------------- stage A: partial DFT over h (k = 0..16) ----------------
// X1[b,k,w,c] = sum_h x[b,h,w,c] * e^{-2pi i k h / 128}
__global__ __launch_bounds__(256) void k_stageA(const float* __restrict__ x) {
    __shared__ float4 sTA[HH*9];
    int b = blockIdx.y, wt = blockIdx.x;
    const float4* gTA4 = (const float4*)g_TA;
    for (int i = threadIdx.x; i < HH*9; i += 256) sTA[i] = gTA4[i];
    __syncthreads();

    int tid = threadIdx.x;
    int c  = tid & 63;
    int w0 = wt*8 + (tid >> 6);
    int w1 = w0 + 4;
    const float* xb = x + (size_t)b * HH * WW * CC;

    float ar0[18], ai0[18], ar1[18], ai1[18];
#pragma unroll
    for (int k = 0; k < 18; k++) { ar0[k]=0.f; ai0[k]=0.f; ar1[k]=0.f; ai1[k]=0.f; }

    for (int h = 0; h < HH; h++) {
        float v0 = xb[((size_t)h*WW + w0)*CC + c];
        float v1 = xb[((size_t)h*WW + w1)*CC + c];
        const float4* ta = &sTA[h*9];
#pragma unroll
        for (int q = 0; q < 9; q++) {
            float4 f = ta[q];
            ar0[2*q]   += v0*f.x;  ai0[2*q]   -= v0*f.y;
            ar0[2*q+1] += v0*f.z;  ai0[2*q+1] -= v0*f.w;
            ar1[2*q]   += v1*f.x;  ai1[2*q]   -= v1*f.y;
            ar1[2*q+1] += v1*f.z;  ai1[2*q+1] -= v1*f.w;
        }
    }
#pragma unroll
    for (int k = 0; k < 17; k++) {
        size_t o0 = ((size_t)(b*NK + k)*WW + w0)*CC + c;
        size_t o1 = ((size_t)(b*NK + k)*WW + w1)*CC + c;
        g_X1re[o0] = ar0[k];  g_X1im[o0] = ai0[k];
        g_X1re[o1] = ar1[k];  g_X1im[o1] = ai1[k];
    }
}

// ---------------- stage B: partial DFT over w, produce 32 kx rows ----------------
// r = k (0..15):  Y = sum_w X1[k,w] e^{-i psi}
// r = 32-k (k=1..16): Y = conj( sum_w X1[k,w] e^{+i psi} )
__global__ __launch_bounds__(256) void k_stageB() {
    __shared__ float4 sTB[WW*8];
    int b = blockIdx.y, k = blockIdx.x;           // k = 0..16
    const float4* gTB4 = (const float4*)g_TB;
    for (int i = threadIdx.x; i < WW*8; i += 256) sTB[i] = gTB4[i];
    __syncthreads();

    int tid = threadIdx.x;
    int c  = tid & 63;
    int kg = tid >> 6;                            // 4 ky each
    const float* xr = g_X1re + (size_t)(b*NK + k)*WW*CC;
    const float* xi = g_X1im + (size_t)(b*NK + k)*WW*CC;

    float ar[4] = {0,0,0,0}, ai[4] = {0,0,0,0};
    float br[4] = {0,0,0,0}, bi[4] = {0,0,0,0};   // bi holds +Im of plus-transform

    for (int w = 0; w < WW; w++) {
        float re = xr[w*CC + c];
        float im = xi[w*CC + c];
        float4 t0 = sTB[w*8 + kg*2];
        float4 t1 = sTB[w*8 + kg*2 + 1];
        float cs[4] = {t0.x, t0.z, t1.x, t1.z};
        float sn[4] = {t0.y, t0.w, t1.y, t1.w};
#pragma unroll
        for (int j = 0; j < 4; j++) {
            ar[j] += re*cs[j] + im*sn[j];
            ai[j] += im*cs[j] - re*sn[j];
            br[j] += re*cs[j] - im*sn[j];
            bi[j] += re*sn[j] + im*cs[j];
        }
    }
    if (k < 16) {
#pragma unroll
        for (int j = 0; j < 4; j++) {
            int ky = kg*4 + j;
            size_t o = ((size_t)(b*32 + k)*MY + ky)*CC + c;
            g_Yre[o] = ar[j];  g_Yim[o] = ai[j];
        }
    }
    if (k >= 1) {
        int r2 = 32 - k;
#pragma unroll
        for (int j = 0; j < 4; j++) {
            int ky = kg*4 + j;
            size_t o = ((size_t)(b*32 + r2)*MY + ky)*CC + c;
            g_Yre[o] = br[j];  g_Yim[o] = -bi[j];
        }
    }
}

// ---------------- stage C: complex mode mixing (per kx,ky GEMM over channels) ----------------
__global__ __launch_bounds__(256) void k_stageC(const float* __restrict__ w1r,
                                                const float* __restrict__ w1i,
                                                const float* __restrict__ w2r,
                                                const float* __restrict__ w2i) {
    __shared__ float2 sY[32*64];     // 16KB
    __shared__ float  sWr[32*64];    // 8KB (i-chunk)
    __shared__ float  sWi[32*64];    // 8KB
    int ky = blockIdx.x, r = blockIdx.y;
    int tid = threadIdx.x;
    int o  = tid & 63;
    int bs = (tid >> 6) * 8;

    for (int i = tid; i < 32*64; i += 256) {
        int bb = i >> 6, ii = i & 63;
        size_t off = ((size_t)(bb*32 + r)*MY + ky)*CC + ii;
        sY[i] = make_float2(g_Yre[off], g_Yim[off]);
    }

    const float* Wr;
    const float* Wi;
    if (r < 16) {
        Wr = w1r + (size_t)((r*16 + ky)*64)*64;
        Wi = w1i + (size_t)((r*16 + ky)*64)*64;
    } else {
        Wr = w2r + (size_t)(((r-16)*16 + ky)*64)*64;
        Wi = w2i + (size_t)(((r-16)*16 + ky)*64)*64;
    }

    float gr[8] = {0,0,0,0,0,0,0,0}, gi[8] = {0,0,0,0,0,0,0,0};
    for (int ic = 0; ic < 2; ic++) {
        __syncthreads();
        for (int i = tid; i < 32*64; i += 256) {
            sWr[i] = Wr[ic*32*64 + i];
            sWi[i] = Wi[ic*32*64 + i];
        }
        __syncthreads();
        for (int ii = 0; ii < 32; ii++) {
            float wr = sWr[ii*64 + o];
            float wi = sWi[ii*64 + o];
            int i = ic*32 + ii;
#pragma unroll
            for (int bb = 0; bb < 8; bb++) {
                float2 y = sY[(bs + bb)*64 + i];
                gr[bb] += y.x*wr - y.y*wi;
                gi[bb] += y.x*wi + y.y*wr;
            }
        }
    }
#pragma unroll
    for (int bb = 0; bb < 8; bb++) {
        size_t off = ((size_t)((bs + bb)*MY + ky)*32 + r)*CC + o;
        g_Gre[off] = gr[bb];
        g_Gim[off] = gi[bb];
    }
}

// ---------------- stage D1: inverse DFT over h ----------------
// M[b,ky,h,c] = sum_r G[b,ky,r,c] * e^{+2pi i kx(r) h/128}
__global__ __launch_bounds__(512) void k_stageD1() {
    __shared__ float2 sG[32*64];     // 16KB
    int ky = blockIdx.x, b = blockIdx.y;
    int tid = threadIdx.x;
    for (int i = tid; i < 32*64; i += 512) {
        size_t off = ((size_t)(b*MY + ky)*32 + (i >> 6))*CC + (i & 63);
        sG[i] = make_float2(g_Gre[off], g_Gim[off]);
    }
    __syncthreads();

    int c  = tid & 63;
    int hg = tid >> 6;               // 0..7, 16 h each
    float mr[16], mi[16];
#pragma unroll
    for (int q = 0; q < 16; q++) { mr[q] = 0.f; mi[q] = 0.f; }

    for (int r = 0; r < 32; r++) {
        float2 g = sG[r*64 + c];
        const float4* tp = (const float4*)(g_TD1 + (size_t)(r*HH + hg*16)*2);
#pragma unroll
        for (int q = 0; q < 8; q++) {
            float4 f = tp[q];
            mr[2*q]   += g.x*f.x - g.y*f.y;
            mi[2*q]   += g.x*f.y + g.y*f.x;
            mr[2*q+1] += g.x*f.z - g.y*f.w;
            mi[2*q+1] += g.x*f.w + g.y*f.z;
        }
    }
#pragma unroll
    for (int hh = 0; hh < 16; hh++) {
        size_t off = ((size_t)(b*MY + ky)*HH + hg*16 + hh)*CC + c;
        g_Mre[off] = mr[hh];
        g_Mim[off] = mi[hh];
    }
}

// ---------------- stage E: inverse DFT over w + dense + bias + residual + GELU ----------------
__global__ __launch_bounds__(256, 2) void k_stageE(const float* __restrict__ x,
                                                   const float* __restrict__ Kd,
                                                   const float* __restrict__ bias,
                                                   float* __restrict__ out) {
    __shared__ __align__(16) float xs[64*CC];   // 16KB: half a row
    __shared__ float4 sTC[WW*4];                // 8KB
    __shared__ float4 sTS[WW*4];                // 8KB
    int h = blockIdx.x, b = blockIdx.y;
    int tid = threadIdx.x;
    int c  = tid & 63;
    int wg = tid >> 6;

    for (int i = tid; i < WW*4; i += 256) {
        sTC[i] = ((const float4*)g_TC)[i];
        sTS[i] = ((const float4*)g_TS)[i];
    }

    float Kc[64];
#pragma unroll
    for (int i = 0; i < 64; i++) Kc[i] = Kd[i*64 + c];

    float sRe[16], sIm[16];
#pragma unroll
    for (int ky = 0; ky < 16; ky++) {
        size_t off = ((size_t)(b*MY + ky)*HH + h)*CC + c;
        sRe[ky] = g_Mre[off];
        sIm[ky] = g_Mim[off];
    }
    float bc = bias[c];
    const float* xrow = x   + ((size_t)(b*HH + h)*WW)*CC;
    float*       orow = out + ((size_t)(b*HH + h)*WW)*CC;

    for (int half = 0; half < 2; half++) {
        __syncthreads();
        for (int i = tid; i < 64*CC/4; i += 256)
            ((float4*)xs)[i] = ((const float4*)(xrow + half*64*CC))[i];
        __syncthreads();

        for (int ww = 0; ww < 16; ww++) {
            int w = wg*16 + ww;             // 0..63 within half
            int wglob = half*64 + w;
            float a0 = bc, a1 = 0.f;

            const float4* xv = (const float4*)&xs[w*CC];
#pragma unroll
            for (int q = 0; q < 16; q++) {
                float4 f = xv[q];
                float tacc = f.x*Kc[4*q] + f.y*Kc[4*q+1] + f.z*Kc[4*q+2] + f.w*Kc[4*q+3];
                if (q & 1) a1 += tacc; else a0 += tacc;
            }
#pragma unroll
            for (int q = 0; q < 4; q++) {
                float4 tc = sTC[wglob*4 + q];
                float4 ts = sTS[wglob*4 + q];
                a0 += tc.x*sRe[4*q]   - ts.x*sIm[4*q];
                a1 += tc.y*sRe[4*q+1] - ts.y*sIm[4*q+1];
                a0 += tc.z*sRe[4*q+2] - ts.z*sIm[4*q+2];
                a1 += tc.w*sRe[4*q+3] - ts.w*sIm[4*q+3];
            }
            float u = xs[w*CC + c] + a0 + a1;
            float u3 = u*u*u;
            float t = tanhf(0.7978845608028654f*(u + 0.044715f*u3));
            orow[(size_t)wglob*CC + c] = 0.5f*u*(1.f + t);
        }
    }
}

// ---------------- launch ----------------
extern "C" void kernel_launch(void* const* d_in, const int* in_sizes, int n_in,
                              void* d_out, int out_size) {
    const float* x    = (const float*)d_in[0];
    const float* w1r  = (const float*)d_in[1];
    const float* w1i  = (const float*)d_in[2];
    const float* w2r  = (const float*)d_in[3];
    const float* w2i  = (const float*)d_in[4];
    const float* Kd   = (const float*)d_in[5];
    const float* bias = (const float*)d_in[6];
    float* out = (float*)d_out;

    k_init<<<32, 256>>>();
    k_stageA<<<dim3(16, 32), 256>>>(x);
    k_stageB<<<dim3(17, 32), 256>>>();
    k_stageC<<<dim3(16, 32), 256>>>(w1r, w1i, w2r, w2i);
    k_stageD1<<<dim3(16, 32), 512>>>();
    k_stageE<<<dim3(128, 32), 256>>>(x, Kd, bias, out);
}

// round 2
// speedup vs baseline: 1.2218x; 1.2218x over previous
#include <cuda_runtime.h>
#include <math.h>

#define BB 32
#define HH 128
#define WW 128
#define CC 64
#define MX 16
#define MY 16
#define NK 17

typedef unsigned long long u64;

__device__ __forceinline__ u64 pk(float a, float b) {
    u64 r; asm("mov.b64 %0, {%1,%2};" : "=l"(r) : "f"(a), "f"(b)); return r;
}
__device__ __forceinline__ float2 upk(u64 v) {
    float2 f; asm("mov.b64 {%0,%1}, %2;" : "=f"(f.x), "=f"(f.y) : "l"(v)); return f;
}
__device__ __forceinline__ void fma2(u64 &d, u64 a, u64 b) {
    asm("fma.rn.f32x2 %0, %1, %2, %0;" : "+l"(d) : "l"(a), "l"(b));
}

// ---------------- scratch ----------------
__device__ __align__(16) u64 g_X1[BB*NK*WW*CC];        // (re,im) interleaved
__device__ __align__(16) u64 g_Y [BB*32*MY*CC];        // (re,im)
__device__ __align__(16) u64 g_G [BB*MY*32*CC];        // (re,im)  [b][ky][r][c]
__device__ __align__(16) float g_Mre[BB*MY*HH*CC];
__device__ __align__(16) float g_Mim[BB*MY*HH*CC];

// twiddle tables (packed)
__device__ __align__(16) u64 g_TA2[HH*18];             // [h][k] pk(cos,-sin), k=17 pad 0
__device__ __align__(16) u64 g_TBc[WW*MY];             // pk(c,c)
__device__ __align__(16) u64 g_TBs[WW*MY];             // pk(s,s)
__device__ __align__(16) ulonglong2 g_TW[128];         // {pk(c,s), pk(-s,c)} angle +2pi m/128
__device__ __align__(16) u64 g_TC2[WW*8];              // pairs of coef*cos over ky
__device__ __align__(16) u64 g_TS2[WW*8];              // pairs of -coef*sin over ky

// ---------------- init ----------------
__global__ void k_init() {
    int t = blockIdx.x * blockDim.x + threadIdx.x;
    int stride = gridDim.x * blockDim.x;
    const float STEP = 6.28318530717958647692f / 128.0f;

    for (int i = t; i < HH*18; i += stride) {
        int h = i / 18, k = i % 18;
        if (k < 17) {
            int m = (k * h) & 127;
            float s, c; sincosf(STEP * (float)m, &s, &c);
            g_TA2[i] = pk(c, -s);
        } else g_TA2[i] = 0ull;
    }
    for (int i = t; i < WW*MY; i += stride) {
        int w = i / MY, ky = i % MY;
        int m = (ky * w) & 127;
        float s, c; sincosf(STEP * (float)m, &s, &c);
        g_TBc[i] = pk(c, c);
        g_TBs[i] = pk(s, s);
    }
    for (int i = t; i < 128; i += stride) {
        float s, c; sincosf(STEP * (float)i, &s, &c);
        g_TW[i].x = pk(c, s);
        g_TW[i].y = pk(-s, c);
    }
    for (int i = t; i < WW*8; i += stride) {
        int w = i / 8, j = i % 8;
        int k0 = 2*j, k1 = 2*j + 1;
        float s0, c0, s1, c1;
        sincosf(STEP * (float)((k0 * w) & 127), &s0, &c0);
        sincosf(STEP * (float)((k1 * w) & 127), &s1, &c1);
        float f0 = ((k0 == 0) ? 1.f : 2.f) / 16384.f;
        float f1 = 2.f / 16384.f;
        g_TC2[i] = pk(f0 * c0, f1 * c1);
        g_TS2[i] = pk(-f0 * s0, -f1 * s1);
    }
}

// ---------------- stage A: partial DFT over h (k = 0..16) ----------------
__global__ __launch_bounds__(256) void k_stageA(const float* __restrict__ x) {
    __shared__ ulonglong2 sTA[HH*9];
    int b = blockIdx.y, wt = blockIdx.x;
    const ulonglong2* gTA = (const ulonglong2*)g_TA2;
    for (int i = threadIdx.x; i < HH*9; i += 256) sTA[i] = gTA[i];
    __syncthreads();

    int tid = threadIdx.x;
    int c  = tid & 63;
    int w0 = wt*8 + (tid >> 6);
    int w1 = w0 + 4;
    const float* xb = x + (size_t)b * HH * WW * CC;

    u64 a0[18], a1[18];
#pragma unroll
    for (int k = 0; k < 18; k++) { a0[k] = 0ull; a1[k] = 0ull; }

    float v0 = xb[(size_t)(0*WW + w0)*CC + c];
    float v1 = xb[(size_t)(0*WW + w1)*CC + c];
    for (int h = 0; h < HH; h++) {
        float n0 = 0.f, n1 = 0.f;
        if (h < 127) {
            n0 = xb[((size_t)(h+1)*WW + w0)*CC + c];
            n1 = xb[((size_t)(h+1)*WW + w1)*CC + c];
        }
        u64 p0 = pk(v0, v0), p1 = pk(v1, v1);
#pragma unroll
        for (int q = 0; q < 9; q++) {
            ulonglong2 tw = sTA[h*9 + q];
            fma2(a0[2*q],   p0, tw.x);
            fma2(a0[2*q+1], p0, tw.y);
            fma2(a1[2*q],   p1, tw.x);
            fma2(a1[2*q+1], p1, tw.y);
        }
        v0 = n0; v1 = n1;
    }
#pragma unroll
    for (int k = 0; k < 17; k++) {
        g_X1[((size_t)(b*NK + k)*WW + w0)*CC + c] = a0[k];
        g_X1[((size_t)(b*NK + k)*WW + w1)*CC + c] = a1[k];
    }
}

// ---------------- stage B: partial DFT over w ----------------
__global__ __launch_bounds__(256) void k_stageB() {
    __shared__ u64 sCC[WW*MY];
    __shared__ u64 sSS[WW*MY];
    int b = blockIdx.y, k = blockIdx.x;   // 0..16
    for (int i = threadIdx.x; i < WW*MY; i += 256) { sCC[i] = g_TBc[i]; sSS[i] = g_TBs[i]; }
    __syncthreads();

    int tid = threadIdx.x;
    int c  = tid & 63;
    int kg = tid >> 6;
    const u64* xp = g_X1 + (size_t)(b*NK + k)*WW*CC;

    u64 aP[4] = {0,0,0,0}, bP[4] = {0,0,0,0};
    for (int w = 0; w < WW; w++) {
        u64 v = xp[w*CC + c];
        float2 f = upk(v);
        u64 vA = pk(f.y, -f.x);
        u64 vB = pk(-f.y, f.x);
#pragma unroll
        for (int j = 0; j < 4; j++) {
            int ky = kg*4 + j;
            u64 cv = sCC[w*MY + ky];
            u64 sv = sSS[w*MY + ky];
            fma2(aP[j], v,  cv);
            fma2(aP[j], vA, sv);
            fma2(bP[j], v,  cv);
            fma2(bP[j], vB, sv);
        }
    }
    if (k < 16) {
#pragma unroll
        for (int j = 0; j < 4; j++) {
            int ky = kg*4 + j;
            g_Y[((size_t)(b*32 + k)*MY + ky)*CC + c] = aP[j];
        }
    }
    if (k >= 1) {
        int r2 = 32 - k;
#pragma unroll
        for (int j = 0; j < 4; j++) {
            int ky = kg*4 + j;
            float2 f = upk(bP[j]);
            g_Y[((size_t)(b*32 + r2)*MY + ky)*CC + c] = pk(f.x, -f.y);
        }
    }
}

// ---------------- stage C: complex mode mixing ----------------
__global__ __launch_bounds__(256) void k_stageC(const float* __restrict__ w1r,
                                                const float* __restrict__ w1i,
                                                const float* __restrict__ w2r,
                                                const float* __restrict__ w2i) {
    __shared__ float sYre[64*34];
    __shared__ float sYim[64*34];
    __shared__ float sWr[32*64];
    __shared__ float sWi[32*64];
    int ky = blockIdx.x, r = blockIdx.y;
    int tid = threadIdx.x;

    for (int idx = tid; idx < 2048; idx += 256) {
        int bb = idx >> 6, cc2 = idx & 63;
        float2 f = upk(g_Y[((size_t)(bb*32 + r)*MY + ky)*CC + cc2]);
        sYre[cc2*34 + bb] = f.x;
        sYim[cc2*34 + bb] = f.y;
    }

    const float* Wr;
    const float* Wi;
    if (r < 16) {
        Wr = w1r + (size_t)((r*16 + ky)*64)*64;
        Wi = w1i + (size_t)((r*16 + ky)*64)*64;
    } else {
        Wr = w2r + (size_t)(((r-16)*16 + ky)*64)*64;
        Wi = w2i + (size_t)(((r-16)*16 + ky)*64)*64;
    }

    int o  = tid & 63;
    int bg = tid >> 6;                 // 4 groups, each 4 bb-pairs (8 batches)
    u64 accR[4] = {0,0,0,0}, accI[4] = {0,0,0,0};

    for (int ic = 0; ic < 2; ic++) {
        __syncthreads();
        for (int i = tid; i < 2048; i += 256) {
            sWr[i] = Wr[ic*2048 + i];
            sWi[i] = Wi[ic*2048 + i];
        }
        __syncthreads();
        for (int ii = 0; ii < 32; ii++) {
            int i = ic*32 + ii;
            float wr = sWr[ii*64 + o];
            float wi = sWi[ii*64 + o];
            u64 wrp = pk(wr,  wr);
            u64 wip = pk(wi,  wi);
            u64 win = pk(-wi, -wi);
#pragma unroll
            for (int bp = 0; bp < 4; bp++) {
                int bb2 = bg*8 + bp*2;
                u64 yr = *(const u64*)&sYre[i*34 + bb2];
                u64 yi = *(const u64*)&sYim[i*34 + bb2];
                fma2(accR[bp], yr, wrp);
                fma2(accR[bp], yi, win);
                fma2(accI[bp], yr, wip);
                fma2(accI[bp], yi, wrp);
            }
        }
    }
#pragma unroll
    for (int bp = 0; bp < 4; bp++) {
        int bb = bg*8 + bp*2;
        float2 R = upk(accR[bp]);
        float2 I = upk(accI[bp]);
        g_G[((size_t)(bb    *MY + ky)*32 + r)*CC + o] = pk(R.x, I.x);
        g_G[((size_t)((bb+1)*MY + ky)*32 + r)*CC + o] = pk(R.y, I.y);
    }
}

// ---------------- stage D1: inverse DFT over h ----------------
__global__ __launch_bounds__(512) void k_stageD1() {
    __shared__ u64 sG[32*64];
    __shared__ ulonglong2 sTW[128];
    int ky = blockIdx.x, b = blockIdx.y;
    int tid = threadIdx.x;
    for (int i = tid; i < 2048; i += 512)
        sG[i] = g_G[((size_t)(b*MY + ky)*32 + (i >> 6))*CC + (i & 63)];
    for (int i = tid; i < 128; i += 512) sTW[i] = g_TW[i];
    __syncthreads();

    int c  = tid & 63;
    int hg = tid >> 6;
    u64 m[16];
#pragma unroll
    for (int q = 0; q < 16; q++) m[q] = 0ull;

    for (int r = 0; r < 32; r++) {
        float2 g = upk(sG[r*64 + c]);
        u64 gx = pk(g.x, g.x);
        u64 gy = pk(g.y, g.y);
        int kx = (r < 16) ? r : (r + 96);       // (kx mod 128), kx<0 -> +128
        int mm = (kx * (hg*16)) & 127;
#pragma unroll
        for (int hh = 0; hh < 16; hh++) {
            ulonglong2 tw = sTW[mm];
            fma2(m[hh], gx, tw.x);
            fma2(m[hh], gy, tw.y);
            mm = (mm + kx) & 127;
        }
    }
#pragma unroll
    for (int hh = 0; hh < 16; hh++) {
        float2 f = upk(m[hh]);
        size_t off = ((size_t)(b*MY + ky)*HH + hg*16 + hh)*CC + c;
        g_Mre[off] = f.x;
        g_Mim[off] = f.y;
    }
}

// ---------------- stage E: inverse DFT over w + dense + bias + residual + GELU ----------------
__global__ __launch_bounds__(256, 2) void k_stageE(const float* __restrict__ x,
                                                   const float* __restrict__ Kd,
                                                   const float* __restrict__ bias,
                                                   float* __restrict__ out) {
    __shared__ __align__(16) u64 xs2[64*32];   // half row: 64 pixels x 64 ch
    __shared__ u64 sTC[WW*8];
    __shared__ u64 sTS[WW*8];
    int h = blockIdx.x, b = blockIdx.y;
    int tid = threadIdx.x;
    int c  = tid & 63;
    int wg = tid >> 6;

    for (int i = tid; i < WW*8; i += 256) { sTC[i] = g_TC2[i]; sTS[i] = g_TS2[i]; }

    u64 Kp[32];
#pragma unroll
    for (int i = 0; i < 32; i++)
        Kp[i] = pk(Kd[(2*i)*64 + c], Kd[(2*i+1)*64 + c]);

    u64 R2[8], I2[8];
#pragma unroll
    for (int j = 0; j < 8; j++) {
        size_t o0 = ((size_t)(b*MY + 2*j    )*HH + h)*CC + c;
        size_t o1 = ((size_t)(b*MY + 2*j + 1)*HH + h)*CC + c;
        R2[j] = pk(g_Mre[o0], g_Mre[o1]);
        I2[j] = pk(g_Mim[o0], g_Mim[o1]);
    }
    float bc = bias[c];
    const float* xrow = x   + ((size_t)(b*HH + h)*WW)*CC;
    float*       orow = out + ((size_t)(b*HH + h)*WW)*CC;

    for (int half = 0; half < 2; half++) {
        __syncthreads();
        for (int i = tid; i < 2048; i += 256)
            xs2[i] = ((const u64*)(xrow + half*64*CC))[i];
        __syncthreads();

        for (int ww = 0; ww < 16; ww++) {
            int w = wg*16 + ww;
            int wglob = half*64 + w;
            u64 acc = 0ull;
            const u64* xv = &xs2[w*32];
#pragma unroll
            for (int i = 0; i < 32; i++) fma2(acc, xv[i], Kp[i]);
#pragma unroll
            for (int j = 0; j < 8; j++) {
                fma2(acc, R2[j], sTC[wglob*8 + j]);
                fma2(acc, I2[j], sTS[wglob*8 + j]);
            }
            float2 s2 = upk(acc);
            float xval = ((const float*)xs2)[w*64 + c];
            float u = xval + bc + s2.x + s2.y;
            float u3 = u*u*u;
            float t = tanhf(0.7978845608028654f*(u + 0.044715f*u3));
            orow[(size_t)wglob*64 + c] = 0.5f*u*(1.f + t);
        }
    }
}

// ---------------- launch ----------------
extern "C" void kernel_launch(void* const* d_in, const int* in_sizes, int n_in,
                              void* d_out, int out_size) {
    const float* x    = (const float*)d_in[0];
    const float* w1r  = (const float*)d_in[1];
    const float* w1i  = (const float*)d_in[2];
    const float* w2r  = (const float*)d_in[3];
    const float* w2i  = (const float*)d_in[4];
    const float* Kd   = (const float*)d_in[5];
    const float* bias = (const float*)d_in[6];
    float* out = (float*)d_out;

    k_init<<<32, 256>>>();
    k_stageA<<<dim3(16, 32), 256>>>(x);
    k_stageB<<<dim3(17, 32), 256>>>();
    k_stageC<<<dim3(16, 32), 256>>>(w1r, w1i, w2r, w2i);
    k_stageD1<<<dim3(16, 32), 512>>>();
    k_stageE<<<dim3(128, 32), 256>>>(x, Kd, bias, out);
}

// round 3
// speedup vs baseline: 1.2994x; 1.0635x over previous
#include <cuda_runtime.h>
#include <math.h>

#define BB 32
#define HH 128
#define WW 128
#define CC 64
#define MX 16
#define MY 16
#define NK 17

typedef unsigned long long u64;

__device__ __forceinline__ u64 pk(float a, float b) {
    u64 r; asm("mov.b64 %0, {%1,%2};" : "=l"(r) : "f"(a), "f"(b)); return r;
}
__device__ __forceinline__ float2 upk(u64 v) {
    float2 f; asm("mov.b64 {%0,%1}, %2;" : "=f"(f.x), "=f"(f.y) : "l"(v)); return f;
}
__device__ __forceinline__ void fma2(u64 &d, u64 a, u64 b) {
    asm("fma.rn.f32x2 %0, %1, %2, %0;" : "+l"(d) : "l"(a), "l"(b));
}
__device__ __forceinline__ float fast_tanh(float x) {
    float t; asm("tanh.approx.f32 %0, %1;" : "=f"(t) : "f"(x)); return t;
}

// ---------------- scratch ----------------
__device__ __align__(16) u64 g_X1[BB*NK*WW*CC];        // (re,im)
__device__ __align__(16) u64 g_Y [BB*32*MY*CC];        // (re,im)
__device__ __align__(16) u64 g_G [BB*MY*32*CC];        // (re,im) [b][ky][r][c]
__device__ __align__(16) float g_Mre[BB*MY*HH*CC];
__device__ __align__(16) float g_Mim[BB*MY*HH*CC];

// twiddle tables
__device__ __align__(16) u64 g_TA2[HH*18];             // [h][k] pk(cos,-sin)
__device__ __align__(16) u64 g_TBc[WW*MY];             // pk(c,c)
__device__ __align__(16) u64 g_TBs[WW*MY];             // pk(s,s)
__device__ __align__(16) ulonglong2 g_TW[128];         // {pk(c,s), pk(-s,c)}
__device__ __align__(16) ulonglong2 g_TP[128];         // {pk(c,c), pk(s,s)}
__device__ __align__(16) u64 g_TC2[WW*8];
__device__ __align__(16) u64 g_TS2[WW*8];

// ---------------- init ----------------
__global__ void k_init() {
    int t = blockIdx.x * blockDim.x + threadIdx.x;
    int stride = gridDim.x * blockDim.x;
    const float STEP = 6.28318530717958647692f / 128.0f;

    for (int i = t; i < HH*18; i += stride) {
        int h = i / 18, k = i % 18;
        if (k < 17) {
            int m = (k * h) & 127;
            float s, c; sincosf(STEP * (float)m, &s, &c);
            g_TA2[i] = pk(c, -s);
        } else g_TA2[i] = 0ull;
    }
    for (int i = t; i < WW*MY; i += stride) {
        int w = i / MY, ky = i % MY;
        int m = (ky * w) & 127;
        float s, c; sincosf(STEP * (float)m, &s, &c);
        g_TBc[i] = pk(c, c);
        g_TBs[i] = pk(s, s);
    }
    for (int i = t; i < 128; i += stride) {
        float s, c; sincosf(STEP * (float)i, &s, &c);
        g_TW[i].x = pk(c, s);
        g_TW[i].y = pk(-s, c);
        g_TP[i].x = pk(c, c);
        g_TP[i].y = pk(s, s);
    }
    for (int i = t; i < WW*8; i += stride) {
        int w = i / 8, j = i % 8;
        int k0 = 2*j, k1 = 2*j + 1;
        float s0, c0, s1, c1;
        sincosf(STEP * (float)((k0 * w) & 127), &s0, &c0);
        sincosf(STEP * (float)((k1 * w) & 127), &s1, &c1);
        float f0 = ((k0 == 0) ? 1.f : 2.f) / 16384.f;
        float f1 = 2.f / 16384.f;
        g_TC2[i] = pk(f0 * c0, f1 * c1);
        g_TS2[i] = pk(-f0 * s0, -f1 * s1);
    }
}

// ---------------- stage A: partial DFT over h (k = 0..16) ----------------
__global__ __launch_bounds__(256) void k_stageA(const float* __restrict__ x) {
    __shared__ ulonglong2 sTA[HH*9];
    int b = blockIdx.y, wt = blockIdx.x;
    const ulonglong2* gTA = (const ulonglong2*)g_TA2;
    for (int i = threadIdx.x; i < HH*9; i += 256) sTA[i] = gTA[i];
    __syncthreads();

    int tid = threadIdx.x;
    int c  = tid & 63;
    int w0 = wt*8 + (tid >> 6);
    int w1 = w0 + 4;
    const float* xb = x + (size_t)b * HH * WW * CC;

    u64 a0[18], a1[18];
#pragma unroll
    for (int k = 0; k < 18; k++) { a0[k] = 0ull; a1[k] = 0ull; }

    float v0 = xb[(size_t)(0*WW + w0)*CC + c];
    float v1 = xb[(size_t)(0*WW + w1)*CC + c];
    for (int h = 0; h < HH; h++) {
        float n0 = 0.f, n1 = 0.f;
        if (h < 127) {
            n0 = xb[((size_t)(h+1)*WW + w0)*CC + c];
            n1 = xb[((size_t)(h+1)*WW + w1)*CC + c];
        }
        u64 p0 = pk(v0, v0), p1 = pk(v1, v1);
#pragma unroll
        for (int q = 0; q < 9; q++) {
            ulonglong2 tw = sTA[h*9 + q];
            fma2(a0[2*q],   p0, tw.x);
            fma2(a0[2*q+1], p0, tw.y);
            fma2(a1[2*q],   p1, tw.x);
            fma2(a1[2*q+1], p1, tw.y);
        }
        v0 = n0; v1 = n1;
    }
#pragma unroll
    for (int k = 0; k < 17; k++) {
        g_X1[((size_t)(b*NK + k)*WW + w0)*CC + c] = a0[k];
        g_X1[((size_t)(b*NK + k)*WW + w1)*CC + c] = a1[k];
    }
}

// ---------------- stage B: partial DFT over w (P/Q shared-term trick) ----------------
__global__ __launch_bounds__(256) void k_stageB() {
    __shared__ __align__(16) u64 sCC[WW*MY];
    __shared__ __align__(16) u64 sSS[WW*MY];
    int b = blockIdx.y, k = blockIdx.x;   // 0..16
    for (int i = threadIdx.x; i < WW*MY; i += 256) { sCC[i] = g_TBc[i]; sSS[i] = g_TBs[i]; }
    __syncthreads();

    int tid = threadIdx.x;
    int c  = tid & 63;
    int kg = tid >> 6;
    const u64* xp = g_X1 + (size_t)(b*NK + k)*WW*CC;

    u64 P[4] = {0,0,0,0}, Q[4] = {0,0,0,0};
    for (int w = 0; w < WW; w++) {
        u64 v = xp[w*CC + c];
        float2 f = upk(v);
        u64 vA = pk(f.y, -f.x);
        const ulonglong2* cp = (const ulonglong2*)&sCC[w*MY + kg*4];
        const ulonglong2* sp = (const ulonglong2*)&sSS[w*MY + kg*4];
        ulonglong2 c01 = cp[0], c23 = cp[1];
        ulonglong2 s01 = sp[0], s23 = sp[1];
        fma2(P[0], v, c01.x);  fma2(Q[0], vA, s01.x);
        fma2(P[1], v, c01.y);  fma2(Q[1], vA, s01.y);
        fma2(P[2], v, c23.x);  fma2(Q[2], vA, s23.x);
        fma2(P[3], v, c23.y);  fma2(Q[3], vA, s23.y);
    }
    if (k < 16) {
#pragma unroll
        for (int j = 0; j < 4; j++) {
            int ky = kg*4 + j;
            float2 p = upk(P[j]), q = upk(Q[j]);
            g_Y[((size_t)(b*32 + k)*MY + ky)*CC + c] = pk(p.x + q.x, p.y + q.y);
        }
    }
    if (k >= 1) {
        int r2 = 32 - k;
#pragma unroll
        for (int j = 0; j < 4; j++) {
            int ky = kg*4 + j;
            float2 p = upk(P[j]), q = upk(Q[j]);
            g_Y[((size_t)(b*32 + r2)*MY + ky)*CC + c] = pk(p.x - q.x, q.y - p.y);
        }
    }
}

// ---------------- stage C: complex mode mixing ----------------
__global__ __launch_bounds__(256) void k_stageC(const float* __restrict__ w1r,
                                                const float* __restrict__ w1i,
                                                const float* __restrict__ w2r,
                                                const float* __restrict__ w2i) {
    __shared__ __align__(16) float sYre[64*36];
    __shared__ __align__(16) float sYim[64*36];
    int ky = blockIdx.x, r = blockIdx.y;
    int tid = threadIdx.x;

    for (int idx = tid; idx < 2048; idx += 256) {
        int bb = idx >> 6, cc2 = idx & 63;
        float2 f = upk(g_Y[((size_t)(bb*32 + r)*MY + ky)*CC + cc2]);
        sYre[cc2*36 + bb] = f.x;
        sYim[cc2*36 + bb] = f.y;
    }
    __syncthreads();

    const float* __restrict__ Wr;
    const float* __restrict__ Wi;
    if (r < 16) {
        Wr = w1r + (size_t)((r*16 + ky)*64)*64;
        Wi = w1i + (size_t)((r*16 + ky)*64)*64;
    } else {
        Wr = w2r + (size_t)(((r-16)*16 + ky)*64)*64;
        Wi = w2i + (size_t)(((r-16)*16 + ky)*64)*64;
    }

    int o  = tid & 63;
    int bg = tid >> 6;
    // P1 = sum yr*wr, P2 = sum yi*wi, P3 = sum yr*wi, P4 = sum yi*wr
    u64 P1[4] = {0,0,0,0}, P2[4] = {0,0,0,0}, P3[4] = {0,0,0,0}, P4[4] = {0,0,0,0};

    for (int i = 0; i < 64; i++) {
        float wr = Wr[i*64 + o];
        float wi = Wi[i*64 + o];
        u64 wrp = pk(wr, wr);
        u64 wip = pk(wi, wi);
        const ulonglong2* yrp = (const ulonglong2*)&sYre[i*36 + bg*8];
        const ulonglong2* yip = (const ulonglong2*)&sYim[i*36 + bg*8];
        ulonglong2 yr01 = yrp[0], yr23 = yrp[1];
        ulonglong2 yi01 = yip[0], yi23 = yip[1];
        fma2(P1[0], yr01.x, wrp);  fma2(P2[0], yi01.x, wip);
        fma2(P3[0], yr01.x, wip);  fma2(P4[0], yi01.x, wrp);
        fma2(P1[1], yr01.y, wrp);  fma2(P2[1], yi01.y, wip);
        fma2(P3[1], yr01.y, wip);  fma2(P4[1], yi01.y, wrp);
        fma2(P1[2], yr23.x, wrp);  fma2(P2[2], yi23.x, wip);
        fma2(P3[2], yr23.x, wip);  fma2(P4[2], yi23.x, wrp);
        fma2(P1[3], yr23.y, wrp);  fma2(P2[3], yi23.y, wip);
        fma2(P3[3], yr23.y, wip);  fma2(P4[3], yi23.y, wrp);
    }
#pragma unroll
    for (int bp = 0; bp < 4; bp++) {
        int bb = bg*8 + bp*2;
        float2 p1 = upk(P1[bp]), p2 = upk(P2[bp]);
        float2 p3 = upk(P3[bp]), p4 = upk(P4[bp]);
        g_G[((size_t)(bb    *MY + ky)*32 + r)*CC + o] = pk(p1.x - p2.x, p3.x + p4.x);
        g_G[((size_t)((bb+1)*MY + ky)*32 + r)*CC + o] = pk(p1.y - p2.y, p3.y + p4.y);
    }
}

// ---------------- stage D1: inverse DFT over h (conjugate-pair halving) ----------------
__global__ __launch_bounds__(512) void k_stageD1() {
    __shared__ __align__(16) u64 sG[32*64];
    __shared__ ulonglong2 sTP[128];
    __shared__ ulonglong2 sTW[128];
    int ky = blockIdx.x, b = blockIdx.y;
    int tid = threadIdx.x;
    for (int i = tid; i < 2048; i += 512)
        sG[i] = g_G[((size_t)(b*MY + ky)*32 + (i >> 6))*CC + (i & 63)];
    for (int i = tid; i < 128; i += 512) { sTP[i] = g_TP[i]; sTW[i] = g_TW[i]; }
    __syncthreads();

    int c  = tid & 63;
    int hg = tid >> 6;
    int h0 = hg * 16;

    u64 m[16];
    u64 g0 = sG[c];                       // r = 0 (kx=0): constant term
#pragma unroll
    for (int q = 0; q < 16; q++) m[q] = g0;

    // pairs (r, 32-r), r = 1..15
    for (int r = 1; r < 16; r++) {
        float2 ga = upk(sG[r*64 + c]);
        float2 gb = upk(sG[(32 - r)*64 + c]);
        u64 S  = pk(ga.x + gb.x, ga.y + gb.y);     // G_a + G_b
        u64 Dp = pk(gb.y - ga.y, ga.x - gb.x);     // (-D_im, D_re), D = G_a - G_b
        int mm = (r * h0) & 127;
#pragma unroll
        for (int hh = 0; hh < 16; hh++) {
            ulonglong2 t = sTP[mm];
            fma2(m[hh], S,  t.x);
            fma2(m[hh], Dp, t.y);
            mm = (mm + r) & 127;
        }
    }
    // r = 16 (kx = -16)
    {
        float2 g = upk(sG[16*64 + c]);
        u64 gx = pk(g.x, g.x);
        u64 gy = pk(g.y, g.y);
        int mm = (112 * h0) & 127;
#pragma unroll
        for (int hh = 0; hh < 16; hh++) {
            ulonglong2 t = sTW[mm];
            fma2(m[hh], gx, t.x);
            fma2(m[hh], gy, t.y);
            mm = (mm + 112) & 127;
        }
    }
#pragma unroll
    for (int hh = 0; hh < 16; hh++) {
        float2 f = upk(m[hh]);
        size_t off = ((size_t)(b*MY + ky)*HH + h0 + hh)*CC + c;
        g_Mre[off] = f.x;
        g_Mim[off] = f.y;
    }
}

// ---------------- stage E: inverse DFT over w + dense + bias + residual + GELU ----------------
__global__ __launch_bounds__(256, 2) void k_stageE(const float* __restrict__ x,
                                                   const float* __restrict__ Kd,
                                                   const float* __restrict__ bias,
                                                   float* __restrict__ out) {
    __shared__ __align__(16) u64 xs2[64*32];
    __shared__ __align__(16) u64 sTC[WW*8];
    __shared__ __align__(16) u64 sTS[WW*8];
    int h = blockIdx.x, b = blockIdx.y;
    int tid = threadIdx.x;
    int c  = tid & 63;
    int wg = tid >> 6;

    for (int i = tid; i < WW*8; i += 256) { sTC[i] = g_TC2[i]; sTS[i] = g_TS2[i]; }

    u64 Kp[32];
#pragma unroll
    for (int i = 0; i < 32; i++)
        Kp[i] = pk(Kd[(2*i)*64 + c], Kd[(2*i+1)*64 + c]);

    u64 R2[8], I2[8];
#pragma unroll
    for (int j = 0; j < 8; j++) {
        size_t o0 = ((size_t)(b*MY + 2*j    )*HH + h)*CC + c;
        size_t o1 = ((size_t)(b*MY + 2*j + 1)*HH + h)*CC + c;
        R2[j] = pk(g_Mre[o0], g_Mre[o1]);
        I2[j] = pk(g_Mim[o0], g_Mim[o1]);
    }
    float bc = bias[c];
    const float* xrow = x   + ((size_t)(b*HH + h)*WW)*CC;
    float*       orow = out + ((size_t)(b*HH + h)*WW)*CC;

    for (int half = 0; half < 2; half++) {
        __syncthreads();
        for (int i = tid; i < 2048; i += 256)
            xs2[i] = ((const u64*)(xrow + half*64*CC))[i];
        __syncthreads();

        for (int ww = 0; ww < 16; ww++) {
            int w = wg*16 + ww;
            int wglob = half*64 + w;
            u64 acc0 = pk(bc, 0.f);
            u64 acc1 = 0ull;
            const ulonglong2* xv = (const ulonglong2*)&xs2[w*32];
#pragma unroll
            for (int t = 0; t < 16; t++) {
                ulonglong2 q = xv[t];
                fma2(acc0, q.x, Kp[2*t]);
                fma2(acc1, q.y, Kp[2*t + 1]);
            }
            const ulonglong2* tcp = (const ulonglong2*)&sTC[wglob*8];
            const ulonglong2* tsp = (const ulonglong2*)&sTS[wglob*8];
#pragma unroll
            for (int t = 0; t < 4; t++) {
                ulonglong2 tc = tcp[t];
                ulonglong2 ts = tsp[t];
                fma2(acc0, R2[2*t],     tc.x);
                fma2(acc1, R2[2*t + 1], tc.y);
                fma2(acc0, I2[2*t],     ts.x);
                fma2(acc1, I2[2*t + 1], ts.y);
            }
            float2 s0 = upk(acc0), s1 = upk(acc1);
            float xval = ((const float*)xs2)[w*64 + c];
            float u = xval + s0.x + s0.y + s1.x + s1.y;
            float u3 = u*u*u;
            float t = fast_tanh(0.7978845608028654f*(u + 0.044715f*u3));
            orow[(size_t)wglob*64 + c] = 0.5f*u*(1.f + t);
        }
    }
}

// ---------------- launch ----------------
extern "C" void kernel_launch(void* const* d_in, const int* in_sizes, int n_in,
                              void* d_out, int out_size) {
    const float* x    = (const float*)d_in[0];
    const float* w1r  = (const float*)d_in[1];
    const float* w1i  = (const float*)d_in[2];
    const float* w2r  = (const float*)d_in[3];
    const float* w2i  = (const float*)d_in[4];
    const float* Kd   = (const float*)d_in[5];
    const float* bias = (const float*)d_in[6];
    float* out = (float*)d_out;

    k_init<<<32, 256>>>();
    k_stageA<<<dim3(16, 32), 256>>>(x);
    k_stageB<<<dim3(17, 32), 256>>>();
    k_stageC<<<dim3(16, 32), 256>>>(w1r, w1i, w2r, w2i);
    k_stageD1<<<dim3(16, 32), 512>>>();
    k_stageE<<<dim3(128, 32), 256>>>(x, Kd, bias, out);
}